// round 16
// baseline (speedup 1.0000x reference)
#include <cuda_runtime.h>
#include <cuda_fp16.h>
#include <cstdint>

#define Bsz 8
#define Tsz 4096
#define Dsz 1024
#define Msz (Bsz*Tsz)          // 32768 rows
#define Nsz 2048               // both gates concatenated
#define CHUNKS 64
#define CLEN (Tsz/CHUNKS)      // 64

#define BM 128
#define BN 128
#define BK 64
#define NITER (Dsz/BK)         // 16
#define NTHREADS 256
#define NSTAGE 3
#define APAD_B 144                         // smem row stride in BYTES (72 halves)
#define A_BYTES (BM*APAD_B)                // 18432
#define B_BYTES (BN*APAD_B)                // 18432
#define STAGE_BYTES (A_BYTES + B_BYTES)    // 36864
#define SMEM_BYTES (NSTAGE*STAGE_BYTES)    // 110592  (x2 CTAs = 221 KB/SM)

// ---------------- scratch ----------------------------------------------------
__device__ __half g_am1[(size_t)Msz*Dsz];     // 1 - a, fp16 (64 MB)
__device__ __half g_bh [(size_t)Msz*Dsz];     // b' = sigmoid(zi)*x, fp16 (64 MB)
__device__ __half g_xh [(size_t)Msz*Dsz];     // fp16 x (64 MB)
__device__ __half g_wh [(size_t)Nsz*Dsz];     // fp16 [Wr; Wi] (4 MB)
__device__ float  g_lsig[Dsz];
__device__ float  g_P[Bsz*CHUNKS*Dsz];
__device__ float  g_S[Bsz*CHUNKS*Dsz];
__device__ float  g_h0[Bsz*CHUNKS*Dsz];

// ---------------- helpers -----------------------------------------------------
__device__ __forceinline__ uint32_t smem_u32(const void* p) {
    uint32_t a;
    asm("{ .reg .u64 t; cvta.to.shared.u64 t, %1; cvt.u32.u64 %0, t; }"
        : "=r"(a) : "l"(p));
    return a;
}
__device__ __forceinline__ void cp16(uint32_t saddr, const void* gaddr) {
    asm volatile("cp.async.cg.shared.global [%0], [%1], 16;"
                 :: "r"(saddr), "l"(gaddr));
}
__device__ __forceinline__ void mma_f16(float* d, const uint32_t* a, const uint32_t* b) {
    asm volatile(
        "mma.sync.aligned.m16n8k16.row.col.f32.f16.f16.f32 "
        "{%0,%1,%2,%3}, {%4,%5,%6,%7}, {%8,%9}, {%0,%1,%2,%3};"
        : "+f"(d[0]), "+f"(d[1]), "+f"(d[2]), "+f"(d[3])
        : "r"(a[0]), "r"(a[1]), "r"(a[2]), "r"(a[3]), "r"(b[0]), "r"(b[1]));
}
__device__ __forceinline__ uint32_t lds32(uint32_t addr) {
    uint32_t v;
    asm volatile("ld.shared.b32 %0, [%1];" : "=r"(v) : "r"(addr));
    return v;
}

// ---------------- prep kernels -------------------------------------------------
__global__ void lsig_kernel(const float* __restrict__ lambd) {
    int i = blockIdx.x * blockDim.x + threadIdx.x;
    if (i < Dsz) g_lsig[i] = -log1pf(expf(-lambd[i]));
}
__global__ void prep_x(const float* __restrict__ x) {
    size_t i = ((size_t)blockIdx.x * 256 + threadIdx.x) * 4;
    float4 v = *(const float4*)(x + i);
    __half2 h0 = __floats2half2_rn(v.x, v.y);
    __half2 h1 = __floats2half2_rn(v.z, v.w);
    uint2 u;
    u.x = *(uint32_t*)&h0;
    u.y = *(uint32_t*)&h1;
    *(uint2*)(g_xh + i) = u;
}
__global__ void prep_w(const float* __restrict__ wr, const float* __restrict__ wi) {
    int row = blockIdx.x;                      // 0..2047
    const float* src = (row < Dsz) ? (wr + (size_t)row * Dsz)
                                   : (wi + (size_t)(row - Dsz) * Dsz);
    __half* dst = g_wh + (size_t)row * Dsz;
    int c = threadIdx.x * 4;
    float4 v = *(const float4*)(src + c);
    __half2 h0 = __floats2half2_rn(v.x, v.y);
    __half2 h1 = __floats2half2_rn(v.z, v.w);
    uint2 u;
    u.x = *(uint32_t*)&h0;
    u.y = *(uint32_t*)&h1;
    *(uint2*)(dst + c) = u;
}

// ------ GEMM: fp16 mma.sync, 8 warps (64x32 tiles), 2 CTAs/SM, BK=64,
//        fragment double-buffered sub-step pipeline ------------------------------
__global__ __launch_bounds__(NTHREADS, 2)
void gemm_tc() {
    extern __shared__ __align__(16) char sm[];
    const int tid = threadIdx.x;
    const int wid = tid >> 5, l = tid & 31;
    const int gq  = l >> 2, tq = l & 3;
    const int warp_m = wid & 1;             // 2 groups x 64 rows
    const int warp_n = wid >> 1;            // 4 groups x 32 cols
    const int m0 = blockIdx.y * BM;
    const int n0 = blockIdx.x * BN;

    float acc[4][4][4];
    #pragma unroll
    for (int mt = 0; mt < 4; mt++)
        #pragma unroll
        for (int nt = 0; nt < 4; nt++)
            #pragma unroll
            for (int q = 0; q < 4; q++) acc[mt][nt][q] = 0.f;

    const uint32_t s0 = smem_u32(sm);

    auto load_stage = [&](int st, int k0) {
        uint32_t sA = s0 + st * STAGE_BYTES;
        uint32_t sB = sA + A_BYTES;
        const __half* ag = g_xh + (size_t)m0 * Dsz + k0 * BK;
        #pragma unroll
        for (int i = 0; i < 4; i++) {            // A: 128 rows x 8 chunks of 16B
            int idx = tid + i * NTHREADS;
            int r = idx >> 3, c = idx & 7;
            cp16(sA + r * APAD_B + c * 16, ag + (size_t)r * Dsz + c * 8);
        }
        #pragma unroll
        for (int i = 0; i < 4; i++) {            // B: 128 rows x 8 chunks of 16B
            int idx = tid + i * NTHREADS;
            int r = idx >> 3, c = idx & 7;
            cp16(sB + r * APAD_B + c * 16,
                 g_wh + (size_t)(n0 + r) * Dsz + k0 * BK + c * 8);
        }
        asm volatile("cp.async.commit_group;" ::: "memory");
    };

    load_stage(0, 0);
    load_stage(1, 1);

    uint32_t af[2][4][4], bf[2][4][2];   // double-buffered fragments

    #pragma unroll 1
    for (int k0 = 0; k0 < NITER; k0++) {
        int s = k0 % NSTAGE;
        if (k0 < NITER - 1)
            asm volatile("cp.async.wait_group 1;" ::: "memory");
        else
            asm volatile("cp.async.wait_group 0;" ::: "memory");
        __syncthreads();

        if (k0 + 2 < NITER) load_stage((k0 + 2) % NSTAGE, k0 + 2);

        uint32_t As = s0 + s * STAGE_BYTES;
        uint32_t Bs = As + A_BYTES;
        uint32_t Ap = As + (warp_m * 64 + gq) * APAD_B + tq * 4;
        uint32_t Bp = Bs + (warp_n * 32 + gq) * APAD_B + tq * 4;

        // prime buffer 0 with sub-step 0
        #pragma unroll
        for (int mt = 0; mt < 4; mt++) {
            uint32_t ap = Ap + mt * 16 * APAD_B;
            af[0][mt][0] = lds32(ap);
            af[0][mt][1] = lds32(ap + 8 * APAD_B);
            af[0][mt][2] = lds32(ap + 16);
            af[0][mt][3] = lds32(ap + 8 * APAD_B + 16);
        }
        #pragma unroll
        for (int nt = 0; nt < 4; nt++) {
            uint32_t bp = Bp + nt * 8 * APAD_B;
            bf[0][nt][0] = lds32(bp);
            bf[0][nt][1] = lds32(bp + 16);
        }

        #pragma unroll
        for (int j = 0; j < 4; j++) {            // pipelined K=16 sub-steps
            int cur = j & 1, nxt = cur ^ 1;
            if (j < 3) {                         // prefetch sub-step j+1
                uint32_t kb = (j + 1) * 32;
                #pragma unroll
                for (int mt = 0; mt < 4; mt++) {
                    uint32_t ap = Ap + mt * 16 * APAD_B + kb;
                    af[nxt][mt][0] = lds32(ap);
                    af[nxt][mt][1] = lds32(ap + 8 * APAD_B);
                    af[nxt][mt][2] = lds32(ap + 16);
                    af[nxt][mt][3] = lds32(ap + 8 * APAD_B + 16);
                }
                #pragma unroll
                for (int nt = 0; nt < 4; nt++) {
                    uint32_t bp = Bp + nt * 8 * APAD_B + kb;
                    bf[nxt][nt][0] = lds32(bp);
                    bf[nxt][nt][1] = lds32(bp + 16);
                }
            }
            #pragma unroll
            for (int mt = 0; mt < 4; mt++)
                #pragma unroll
                for (int nt = 0; nt < 4; nt++)
                    mma_f16(acc[mt][nt], af[cur][mt], bf[cur][nt]);
        }
    }

    // --- epilogue ---
    const bool is_r = (n0 < Dsz);
    #pragma unroll
    for (int mt = 0; mt < 4; mt++) {
        #pragma unroll
        for (int nt = 0; nt < 4; nt++) {
            int col = n0 + warp_n * 32 + nt * 8 + 2 * tq;
            #pragma unroll
            for (int h = 0; h < 2; h++) {
                int row = m0 + warp_m * 64 + mt * 16 + gq + 8 * h;
                float z0 = acc[mt][nt][2 * h + 0];
                float z1 = acc[mt][nt][2 * h + 1];
                if (is_r) {
                    float ls0 = __ldg(&g_lsig[col]);
                    float ls1 = __ldg(&g_lsig[col + 1]);
                    float r0 = __fdividef(1.f, 1.f + __expf(-z0));
                    float r1 = __fdividef(1.f, 1.f + __expf(-z1));
                    float a0 = __expf(8.f * r0 * ls0);
                    float a1 = __expf(8.f * r1 * ls1);
                    __half2 am = __floats2half2_rn(1.f - a0, 1.f - a1);
                    __stcs((__half2*)(g_am1 + (size_t)row * Dsz + col), am);
                } else {
                    int ce = col - Dsz;
                    float2 xv = __half22float2(
                        *(const __half2*)(g_xh + (size_t)row * Dsz + ce));
                    float i0 = __fdividef(1.f, 1.f + __expf(-z0));
                    float i1 = __fdividef(1.f, 1.f + __expf(-z1));
                    __half2 bv = __floats2half2_rn(i0 * xv.x, i1 * xv.y);
                    __stcs((__half2*)(g_bh + (size_t)row * Dsz + ce), bv);
                }
            }
        }
    }
}

// ---------------- scan kernels --------------------------------------------------
__global__ void scan_reduce() {
    int g = blockIdx.x * blockDim.x + threadIdx.x;   // 262144 threads
    int e = (g & 511) * 2;
    int rest = g >> 9;
    int c = rest & (CHUNKS - 1);
    int b = rest >> 6;
    size_t base = ((size_t)(b * Tsz + c * CLEN)) * Dsz + e;
    float2 P = make_float2(1.f, 1.f), H = make_float2(0.f, 0.f);
    #pragma unroll 8
    for (int t = 0; t < CLEN; t++) {
        float2 am = __half22float2(__ldcs((const __half2*)(g_am1 + base + (size_t)t * Dsz)));
        float2 bp = __half22float2(__ldcs((const __half2*)(g_bh  + base + (size_t)t * Dsz)));
        float a0 = 1.f - am.x, a1 = 1.f - am.y;
        H.x = fmaf(a0, H.x, sqrtf(fmaxf(am.x * (2.f - am.x), 0.f)) * bp.x);
        H.y = fmaf(a1, H.y, sqrtf(fmaxf(am.y * (2.f - am.y), 0.f)) * bp.y);
        P.x *= a0; P.y *= a1;
    }
    size_t idx = (size_t)(b * CHUNKS + c) * Dsz + e;
    *(float2*)(g_P + idx) = P;
    *(float2*)(g_S + idx) = H;
}

// one warp per (batch, channel): shfl Kogge-Stone scan over 64 chunks
__global__ void scan_chunks() {
    int g = blockIdx.x * blockDim.x + threadIdx.x;   // 262144 threads
    int w = g >> 5;                                  // 8192 warps
    int lane = g & 31;
    int e = w & (Dsz - 1);
    int b = w >> 10;
    int c0 = lane * 2;
    size_t i0 = (size_t)(b * CHUNKS + c0) * Dsz + e;
    size_t i1 = i0 + Dsz;
    float P0 = g_P[i0], S0 = g_S[i0];
    float P1 = g_P[i1], S1 = g_S[i1];
    float Pl = P0 * P1;
    float Sl = fmaf(P1, S0, S1);
    #pragma unroll
    for (int d = 1; d < 32; d <<= 1) {
        float Pp = __shfl_up_sync(0xffffffffu, Pl, d);
        float Sp = __shfl_up_sync(0xffffffffu, Sl, d);
        if (lane >= d) {
            Sl = fmaf(Pl, Sp, Sl);
            Pl = Pl * Pp;
        }
    }
    float hprev = __shfl_up_sync(0xffffffffu, Sl, 1);
    if (lane == 0) hprev = 0.f;
    g_h0[i0] = hprev;
    g_h0[i1] = fmaf(P0, hprev, S0);
}

__global__ void scan_apply(float* __restrict__ out) {
    int g = blockIdx.x * blockDim.x + threadIdx.x;   // 262144 threads
    int e = (g & 511) * 2;
    int rest = g >> 9;
    int c = rest & (CHUNKS - 1);
    int b = rest >> 6;
    size_t base = ((size_t)(b * Tsz + c * CLEN)) * Dsz + e;
    float2 h = *(const float2*)(g_h0 + (size_t)(b * CHUNKS + c) * Dsz + e);
    #pragma unroll 8
    for (int t = 0; t < CLEN; t++) {
        float2 am = __half22float2(__ldcs((const __half2*)(g_am1 + base + (size_t)t * Dsz)));
        float2 bp = __half22float2(__ldcs((const __half2*)(g_bh  + base + (size_t)t * Dsz)));
        float a0 = 1.f - am.x, a1 = 1.f - am.y;
        h.x = fmaf(a0, h.x, sqrtf(fmaxf(am.x * (2.f - am.x), 0.f)) * bp.x);
        h.y = fmaf(a1, h.y, sqrtf(fmaxf(am.y * (2.f - am.y), 0.f)) * bp.y);
        __stcs((float2*)(out + base + (size_t)t * Dsz), h);
    }
}

// ---------------- launch --------------------------------------------------------
extern "C" void kernel_launch(void* const* d_in, const int* in_sizes, int n_in,
                              void* d_out, int out_size) {
    (void)in_sizes; (void)n_in; (void)out_size;
    const float* x     = (const float*)d_in[0];
    const float* Wr    = (const float*)d_in[1];
    const float* Wi    = (const float*)d_in[2];
    const float* lambd = (const float*)d_in[3];
    float* out = (float*)d_out;

    static bool attr_set = false;
    if (!attr_set) {
        cudaFuncSetAttribute(gemm_tc, cudaFuncAttributeMaxDynamicSharedMemorySize,
                             SMEM_BYTES);
        attr_set = true;
    }

    lsig_kernel<<<4, 256>>>(lambd);
    prep_x<<<(Msz * Dsz) / 1024, 256>>>(x);
    prep_w<<<Nsz, 256>>>(Wr, Wi);

    dim3 grid(Nsz / BN, Msz / BM);   // (16, 256) = 4096 CTAs
    gemm_tc<<<grid, NTHREADS, SMEM_BYTES>>>();

    scan_reduce<<<1024, 256>>>();
    scan_chunks<<<1024, 256>>>();
    scan_apply<<<1024, 256>>>(out);
}

// round 17
// speedup vs baseline: 1.0142x; 1.0142x over previous
#include <cuda_runtime.h>
#include <cuda_fp16.h>
#include <cstdint>

#define Bsz 8
#define Tsz 4096
#define Dsz 1024
#define Msz (Bsz*Tsz)          // 32768 rows
#define Nsz 2048               // both gates concatenated
#define CHUNKS 128
#define CLEN (Tsz/CHUNKS)      // 32

#define BM 128
#define BN 128
#define BK 64
#define NITER (Dsz/BK)         // 16
#define NTHREADS 256
#define NSTAGE 3
#define APAD_B 144                         // smem row stride in BYTES (72 halves)
#define A_BYTES (BM*APAD_B)                // 18432
#define B_BYTES (BN*APAD_B)                // 18432
#define STAGE_BYTES (A_BYTES + B_BYTES)    // 36864
#define SMEM_BYTES (NSTAGE*STAGE_BYTES)    // 110592  (x2 CTAs = 221 KB/SM)

// ---------------- scratch ----------------------------------------------------
__device__ __half g_am1[(size_t)Msz*Dsz];     // 1 - a, fp16 (64 MB)
__device__ __half g_bh [(size_t)Msz*Dsz];     // b' = sigmoid(zi)*x, fp16 (64 MB)
__device__ __half g_xh [(size_t)Msz*Dsz];     // fp16 x (64 MB)
__device__ __half g_wh [(size_t)Nsz*Dsz];     // fp16 [Wr; Wi] (4 MB)
__device__ float  g_lsig[Dsz];
__device__ float  g_P[Bsz*CHUNKS*Dsz];        // 4 MB
__device__ float  g_S[Bsz*CHUNKS*Dsz];        // 4 MB
__device__ float  g_h0[Bsz*CHUNKS*Dsz];       // 4 MB

// ---------------- helpers -----------------------------------------------------
__device__ __forceinline__ uint32_t smem_u32(const void* p) {
    uint32_t a;
    asm("{ .reg .u64 t; cvta.to.shared.u64 t, %1; cvt.u32.u64 %0, t; }"
        : "=r"(a) : "l"(p));
    return a;
}
__device__ __forceinline__ void cp16(uint32_t saddr, const void* gaddr) {
    asm volatile("cp.async.cg.shared.global [%0], [%1], 16;"
                 :: "r"(saddr), "l"(gaddr));
}
__device__ __forceinline__ void mma_f16(float* d, const uint32_t* a, const uint32_t* b) {
    asm volatile(
        "mma.sync.aligned.m16n8k16.row.col.f32.f16.f16.f32 "
        "{%0,%1,%2,%3}, {%4,%5,%6,%7}, {%8,%9}, {%0,%1,%2,%3};"
        : "+f"(d[0]), "+f"(d[1]), "+f"(d[2]), "+f"(d[3])
        : "r"(a[0]), "r"(a[1]), "r"(a[2]), "r"(a[3]), "r"(b[0]), "r"(b[1]));
}
__device__ __forceinline__ uint32_t lds32(uint32_t addr) {
    uint32_t v;
    asm volatile("ld.shared.b32 %0, [%1];" : "=r"(v) : "r"(addr));
    return v;
}

// ---------------- fused prep kernel ---------------------------------------------
// blocks [0, 32768):       x -> fp16
// blocks [32768, 34816):   [Wr;Wi] -> fp16
// blocks [34816, 34820):   log_sigmoid(lambd)
__global__ void prep_all(const float* __restrict__ x,
                         const float* __restrict__ wr,
                         const float* __restrict__ wi,
                         const float* __restrict__ lambd) {
    int blk = blockIdx.x;
    int tid = threadIdx.x;
    if (blk < 32768) {
        size_t i = ((size_t)blk * 256 + tid) * 4;
        float4 v = *(const float4*)(x + i);
        __half2 h0 = __floats2half2_rn(v.x, v.y);
        __half2 h1 = __floats2half2_rn(v.z, v.w);
        uint2 u;
        u.x = *(uint32_t*)&h0;
        u.y = *(uint32_t*)&h1;
        *(uint2*)(g_xh + i) = u;
    } else if (blk < 32768 + 2048) {
        int row = blk - 32768;                 // 0..2047
        const float* src = (row < Dsz) ? (wr + (size_t)row * Dsz)
                                       : (wi + (size_t)(row - Dsz) * Dsz);
        __half* dst = g_wh + (size_t)row * Dsz;
        int c = tid * 4;
        float4 v = *(const float4*)(src + c);
        __half2 h0 = __floats2half2_rn(v.x, v.y);
        __half2 h1 = __floats2half2_rn(v.z, v.w);
        uint2 u;
        u.x = *(uint32_t*)&h0;
        u.y = *(uint32_t*)&h1;
        *(uint2*)(dst + c) = u;
    } else {
        int i = (blk - 32768 - 2048) * 256 + tid;
        if (i < Dsz) g_lsig[i] = -log1pf(expf(-lambd[i]));
    }
}

// ------ GEMM: fp16 mma.sync, 8 warps (64x32 tiles), 2 CTAs/SM, BK=64 ------------
__global__ __launch_bounds__(NTHREADS, 2)
void gemm_tc() {
    extern __shared__ __align__(16) char sm[];
    const int tid = threadIdx.x;
    const int wid = tid >> 5, l = tid & 31;
    const int gq  = l >> 2, tq = l & 3;
    const int warp_m = wid & 1;             // 2 groups x 64 rows
    const int warp_n = wid >> 1;            // 4 groups x 32 cols
    const int m0 = blockIdx.y * BM;
    const int n0 = blockIdx.x * BN;

    float acc[4][4][4];
    #pragma unroll
    for (int mt = 0; mt < 4; mt++)
        #pragma unroll
        for (int nt = 0; nt < 4; nt++)
            #pragma unroll
            for (int q = 0; q < 4; q++) acc[mt][nt][q] = 0.f;

    const uint32_t s0 = smem_u32(sm);

    auto load_stage = [&](int st, int k0) {
        uint32_t sA = s0 + st * STAGE_BYTES;
        uint32_t sB = sA + A_BYTES;
        const __half* ag = g_xh + (size_t)m0 * Dsz + k0 * BK;
        #pragma unroll
        for (int i = 0; i < 4; i++) {            // A: 128 rows x 8 chunks of 16B
            int idx = tid + i * NTHREADS;
            int r = idx >> 3, c = idx & 7;
            cp16(sA + r * APAD_B + c * 16, ag + (size_t)r * Dsz + c * 8);
        }
        #pragma unroll
        for (int i = 0; i < 4; i++) {            // B: 128 rows x 8 chunks of 16B
            int idx = tid + i * NTHREADS;
            int r = idx >> 3, c = idx & 7;
            cp16(sB + r * APAD_B + c * 16,
                 g_wh + (size_t)(n0 + r) * Dsz + k0 * BK + c * 8);
        }
        asm volatile("cp.async.commit_group;" ::: "memory");
    };

    load_stage(0, 0);
    load_stage(1, 1);

    #pragma unroll 1
    for (int k0 = 0; k0 < NITER; k0++) {
        int s = k0 % NSTAGE;
        if (k0 < NITER - 1)
            asm volatile("cp.async.wait_group 1;" ::: "memory");
        else
            asm volatile("cp.async.wait_group 0;" ::: "memory");
        __syncthreads();

        if (k0 + 2 < NITER) load_stage((k0 + 2) % NSTAGE, k0 + 2);

        uint32_t As = s0 + s * STAGE_BYTES;
        uint32_t Bs = As + A_BYTES;

        #pragma unroll
        for (int kk = 0; kk < 4; kk++) {         // 4 K=16 sub-steps
            uint32_t kb = kk * 32 + tq * 4;      // byte offset within 128B row
            uint32_t af[4][4], bf[4][2];
            #pragma unroll
            for (int mt = 0; mt < 4; mt++) {
                uint32_t ap = As + (warp_m * 64 + mt * 16 + gq) * APAD_B + kb;
                af[mt][0] = lds32(ap);
                af[mt][1] = lds32(ap + 8 * APAD_B);
                af[mt][2] = lds32(ap + 16);
                af[mt][3] = lds32(ap + 8 * APAD_B + 16);
            }
            #pragma unroll
            for (int nt = 0; nt < 4; nt++) {
                uint32_t bp = Bs + (warp_n * 32 + nt * 8 + gq) * APAD_B + kb;
                bf[nt][0] = lds32(bp);
                bf[nt][1] = lds32(bp + 16);
            }
            #pragma unroll
            for (int mt = 0; mt < 4; mt++)
                #pragma unroll
                for (int nt = 0; nt < 4; nt++)
                    mma_f16(acc[mt][nt], af[mt], bf[nt]);
        }
    }

    // --- epilogue ---
    const bool is_r = (n0 < Dsz);
    #pragma unroll
    for (int mt = 0; mt < 4; mt++) {
        #pragma unroll
        for (int nt = 0; nt < 4; nt++) {
            int col = n0 + warp_n * 32 + nt * 8 + 2 * tq;
            #pragma unroll
            for (int h = 0; h < 2; h++) {
                int row = m0 + warp_m * 64 + mt * 16 + gq + 8 * h;
                float z0 = acc[mt][nt][2 * h + 0];
                float z1 = acc[mt][nt][2 * h + 1];
                if (is_r) {
                    float ls0 = __ldg(&g_lsig[col]);
                    float ls1 = __ldg(&g_lsig[col + 1]);
                    float r0 = __fdividef(1.f, 1.f + __expf(-z0));
                    float r1 = __fdividef(1.f, 1.f + __expf(-z1));
                    float a0 = __expf(8.f * r0 * ls0);
                    float a1 = __expf(8.f * r1 * ls1);
                    __half2 am = __floats2half2_rn(1.f - a0, 1.f - a1);
                    __stcs((__half2*)(g_am1 + (size_t)row * Dsz + col), am);
                } else {
                    int ce = col - Dsz;
                    float2 xv = __half22float2(
                        *(const __half2*)(g_xh + (size_t)row * Dsz + ce));
                    float i0 = __fdividef(1.f, 1.f + __expf(-z0));
                    float i1 = __fdividef(1.f, 1.f + __expf(-z1));
                    __half2 bv = __floats2half2_rn(i0 * xv.x, i1 * xv.y);
                    __stcs((__half2*)(g_bh + (size_t)row * Dsz + ce), bv);
                }
            }
        }
    }
}

// ---------------- scan kernels (128 chunks of 32) ---------------------------------
__global__ void scan_reduce() {
    int g = blockIdx.x * blockDim.x + threadIdx.x;   // 524288 threads
    int e = (g & 511) * 2;
    int rest = g >> 9;
    int c = rest & (CHUNKS - 1);
    int b = rest >> 7;
    size_t base = ((size_t)(b * Tsz + c * CLEN)) * Dsz + e;
    float2 P = make_float2(1.f, 1.f), H = make_float2(0.f, 0.f);
    #pragma unroll 8
    for (int t = 0; t < CLEN; t++) {
        float2 am = __half22float2(__ldcs((const __half2*)(g_am1 + base + (size_t)t * Dsz)));
        float2 bp = __half22float2(__ldcs((const __half2*)(g_bh  + base + (size_t)t * Dsz)));
        float a0 = 1.f - am.x, a1 = 1.f - am.y;
        H.x = fmaf(a0, H.x, sqrtf(fmaxf(am.x * (2.f - am.x), 0.f)) * bp.x);
        H.y = fmaf(a1, H.y, sqrtf(fmaxf(am.y * (2.f - am.y), 0.f)) * bp.y);
        P.x *= a0; P.y *= a1;
    }
    size_t idx = (size_t)(b * CHUNKS + c) * Dsz + e;
    *(float2*)(g_P + idx) = P;
    *(float2*)(g_S + idx) = H;
}

// one warp per (batch, channel): lane owns 4 chunks, shfl Kogge-Stone across lanes
__global__ void scan_chunks() {
    int g = blockIdx.x * blockDim.x + threadIdx.x;   // 262144 threads
    int w = g >> 5;                                  // 8192 warps
    int lane = g & 31;
    int e = w & (Dsz - 1);
    int b = w >> 10;
    size_t ibase = ((size_t)b * CHUNKS + lane * 4) * Dsz + e;
    float P[4], S[4];
    #pragma unroll
    for (int i = 0; i < 4; i++) {
        P[i] = g_P[ibase + (size_t)i * Dsz];
        S[i] = g_S[ibase + (size_t)i * Dsz];
    }
    // combine lane's 4 chunks
    float Pl = P[0], Sl = S[0];
    #pragma unroll
    for (int i = 1; i < 4; i++) {
        Sl = fmaf(P[i], Sl, S[i]);
        Pl *= P[i];
    }
    // Kogge-Stone inclusive scan across lanes
    #pragma unroll
    for (int d = 1; d < 32; d <<= 1) {
        float Pp = __shfl_up_sync(0xffffffffu, Pl, d);
        float Sp = __shfl_up_sync(0xffffffffu, Sl, d);
        if (lane >= d) {
            Sl = fmaf(Pl, Sp, Sl);
            Pl = Pl * Pp;
        }
    }
    float h = __shfl_up_sync(0xffffffffu, Sl, 1);
    if (lane == 0) h = 0.f;
    #pragma unroll
    for (int i = 0; i < 4; i++) {
        g_h0[ibase + (size_t)i * Dsz] = h;
        h = fmaf(P[i], h, S[i]);
    }
}

__global__ void scan_apply(float* __restrict__ out) {
    int g = blockIdx.x * blockDim.x + threadIdx.x;   // 524288 threads
    int e = (g & 511) * 2;
    int rest = g >> 9;
    int c = rest & (CHUNKS - 1);
    int b = rest >> 7;
    size_t base = ((size_t)(b * Tsz + c * CLEN)) * Dsz + e;
    float2 h = *(const float2*)(g_h0 + (size_t)(b * CHUNKS + c) * Dsz + e);
    #pragma unroll 8
    for (int t = 0; t < CLEN; t++) {
        float2 am = __half22float2(__ldcs((const __half2*)(g_am1 + base + (size_t)t * Dsz)));
        float2 bp = __half22float2(__ldcs((const __half2*)(g_bh  + base + (size_t)t * Dsz)));
        float a0 = 1.f - am.x, a1 = 1.f - am.y;
        h.x = fmaf(a0, h.x, sqrtf(fmaxf(am.x * (2.f - am.x), 0.f)) * bp.x);
        h.y = fmaf(a1, h.y, sqrtf(fmaxf(am.y * (2.f - am.y), 0.f)) * bp.y);
        __stcs((float2*)(out + base + (size_t)t * Dsz), h);
    }
}

// ---------------- launch --------------------------------------------------------
extern "C" void kernel_launch(void* const* d_in, const int* in_sizes, int n_in,
                              void* d_out, int out_size) {
    (void)in_sizes; (void)n_in; (void)out_size;
    const float* x     = (const float*)d_in[0];
    const float* Wr    = (const float*)d_in[1];
    const float* Wi    = (const float*)d_in[2];
    const float* lambd = (const float*)d_in[3];
    float* out = (float*)d_out;

    static bool attr_set = false;
    if (!attr_set) {
        cudaFuncSetAttribute(gemm_tc, cudaFuncAttributeMaxDynamicSharedMemorySize,
                             SMEM_BYTES);
        attr_set = true;
    }

    prep_all<<<32768 + 2048 + 4, 256>>>(x, Wr, Wi, lambd);

    dim3 grid(Nsz / BN, Msz / BM);   // (16, 256) = 4096 CTAs
    gemm_tc<<<grid, NTHREADS, SMEM_BYTES>>>();

    scan_reduce<<<2048, 256>>>();
    scan_chunks<<<1024, 256>>>();
    scan_apply<<<2048, 256>>>(out);
}